// round 11
// baseline (speedup 1.0000x reference)
#include <cuda_runtime.h>
#include <cstdint>

// path[row][t] = 0.3 + (lam0[row] - 0.3) * 0.5^t   (closed form of the scan;
// clamp inactive after step 0; 0.5^t exact power of two via exponent bits).
//
// R11: single change vs R10 (best, 23.04us): GRID 4096 -> 8192 (ITERS 8 -> 4).
// Grid axis has two consecutive wins from halving last-wave imbalance
// (2048: 14v13 ~7% -> 4096: 28v27 ~3.6% -> 8192: 56v55 ~1.8%). Store MLP per
// SM unchanged (occupancy-limited); probing the diminishing-returns end.
// Store policy fixed by measurement at __stcs (wb 25.06 / cs 23.84 / wt 26.21).

static constexpr int HORIZON = 256;
static constexpr int T4_PER_ROW = HORIZON / 4;       // 64 float4 per row
static constexpr unsigned GRID = 8192;
static constexpr unsigned BLOCK = 256;
static constexpr unsigned STRIDE = GRID * BLOCK;     // 2097152 = 2^21, multiple of 64
static constexpr unsigned N4 = 131072u * T4_PER_ROW; // 2^23 float4 total
static constexpr int ITERS = N4 / STRIDE;            // exactly 4

__global__ __launch_bounds__(BLOCK) void lyap_path_kernel(
    const float* __restrict__ lam0, float* __restrict__ out)
{
    unsigned idx4 = blockIdx.x * BLOCK + threadIdx.x;

    // Loop-invariant: t = 4 * (idx4 % 64) is fixed per thread (STRIDE % 64 == 0).
    int t = (int)(idx4 & (T4_PER_ROW - 1)) << 2;
    int e = 127 - t;
    const float f0 = (e > 0) ? __uint_as_float((unsigned)e << 23) : 0.0f;
    const float f1 = f0 * 0.5f;
    const float f2 = f1 * 0.5f;
    const float f3 = f2 * 0.5f;

    float4* __restrict__ out4 = reinterpret_cast<float4*>(out);
    const unsigned row_stride = STRIDE / T4_PER_ROW;  // 32768
    unsigned row = idx4 >> 6;

    #pragma unroll
    for (int i = 0; i < ITERS; i++, idx4 += STRIDE, row += row_stride) {
        float diff = __ldg(&lam0[row]) - 0.3f;

        float4 v;
        v.x = fmaf(diff, f0, 0.3f);
        v.y = fmaf(diff, f1, 0.3f);
        v.z = fmaf(diff, f2, 0.3f);
        v.w = fmaf(diff, f3, 0.3f);

        __stcs(&out4[idx4], v);   // evict-first: overlap writeback with next replay
    }
}

extern "C" void kernel_launch(void* const* d_in, const int* in_sizes, int n_in,
                              void* d_out, int out_size)
{
    const float* lam0 = (const float*)d_in[0];
    float* out = (float*)d_out;

    lyap_path_kernel<<<GRID, BLOCK>>>(lam0, out);
}

// round 12
// speedup vs baseline: 1.3556x; 1.3556x over previous
#include <cuda_runtime.h>
#include <cstdint>

// path[row][t] = 0.3 + (lam0[row] - 0.3) * 0.5^t   (closed form of the scan;
// clamp inactive after step 0; 0.5^t exact power of two via exponent bits).
//
// R12: revert to R10 (best, 23.04us) + reproducibility re-bench.
// Measured optima, bracketed:
//   grid:  2048 -> 23.84 | 4096 -> 23.04 | 8192 -> 31.23 (L1tex-queue cliff:
//          short 4-deep front-batched store bursts from 2x CTAs/SM saturate
//          the L1 wavefront queue -- L1 71%, L2/DRAM collapsed)
//   store: write-back 25.06 | __stcs 23.84..23.04 | __stwt 26.21
//   loop:  exact 8 iterations (2^20 stride divides n4=2^23), hoisted
//          loop-invariant decay factors, STG.128.

static constexpr int HORIZON = 256;
static constexpr int T4_PER_ROW = HORIZON / 4;       // 64 float4 per row
static constexpr unsigned GRID = 4096;
static constexpr unsigned BLOCK = 256;
static constexpr unsigned STRIDE = GRID * BLOCK;     // 1048576 = 2^20, multiple of 64
static constexpr unsigned N4 = 131072u * T4_PER_ROW; // 2^23 float4 total
static constexpr int ITERS = N4 / STRIDE;            // exactly 8

__global__ __launch_bounds__(BLOCK) void lyap_path_kernel(
    const float* __restrict__ lam0, float* __restrict__ out)
{
    unsigned idx4 = blockIdx.x * BLOCK + threadIdx.x;

    // Loop-invariant: t = 4 * (idx4 % 64) is fixed per thread (STRIDE % 64 == 0).
    int t = (int)(idx4 & (T4_PER_ROW - 1)) << 2;
    int e = 127 - t;
    const float f0 = (e > 0) ? __uint_as_float((unsigned)e << 23) : 0.0f;
    const float f1 = f0 * 0.5f;
    const float f2 = f1 * 0.5f;
    const float f3 = f2 * 0.5f;

    float4* __restrict__ out4 = reinterpret_cast<float4*>(out);
    const unsigned row_stride = STRIDE / T4_PER_ROW;  // 16384
    unsigned row = idx4 >> 6;

    #pragma unroll
    for (int i = 0; i < ITERS; i++, idx4 += STRIDE, row += row_stride) {
        float diff = __ldg(&lam0[row]) - 0.3f;

        float4 v;
        v.x = fmaf(diff, f0, 0.3f);
        v.y = fmaf(diff, f1, 0.3f);
        v.z = fmaf(diff, f2, 0.3f);
        v.w = fmaf(diff, f3, 0.3f);

        __stcs(&out4[idx4], v);   // evict-first: overlap writeback with next replay
    }
}

extern "C" void kernel_launch(void* const* d_in, const int* in_sizes, int n_in,
                              void* d_out, int out_size)
{
    const float* lam0 = (const float*)d_in[0];
    float* out = (float*)d_out;

    lyap_path_kernel<<<GRID, BLOCK>>>(lam0, out);
}